// round 7
// baseline (speedup 1.0000x reference)
#include <cuda_runtime.h>
#include <cuda_bf16.h>
#include <cstdint>

// CrossPatchModule closed form (forward):
//   out[b,c,h,w] = x[b,c, (m>>3)*64 + (h&63), (m&7)*64 + (w&63)] + ap[c*64+m]
//   with m = (c + (h>>6)*8 + (w>>6)) & 63
//
// R5: persistent grid-stride version of R3 (sequential streaming reads,
// 256B-coalesced scattered writes). Exactly 148*8 = 1184 CTAs -> zero wave
// transitions, no partial-wave tail, loads continuously in flight.
// MLP=4 per thread per iteration, streaming cache hints, 32 regs (occ 8).

#define N_F4      16777216u           // 4*64*512*512 / 4
#define CHUNK     1024u               // float4 per block-iteration (256 thr * 4)
#define NBLK      1184u               // 148 SMs * 8 CTAs
#define STRIDE    (NBLK * CHUNK)

__global__ __launch_bounds__(256, 8)
void crosspatch_kernel(const float4* __restrict__ x,
                       const float*  __restrict__ ap,
                       float4*       __restrict__ out)
{
    for (unsigned t0 = blockIdx.x * CHUNK + threadIdx.x; t0 < N_F4; t0 += STRIDE) {
        float4   v[4];
        unsigned dst[4];
        float    add[4];

#pragma unroll
        for (int k = 0; k < 4; ++k)
            v[k] = __ldcs(&x[t0 + k * 256u]);      // sequential streaming read

#pragma unroll
        for (int k = 0; k < 4; ++k) {
            unsigned t   = t0 + k * 256u;
            unsigned w4  = t & 127u;               // src float4-col (128/row)
            unsigned sh  = (t >> 7) & 511u;        // src row
            unsigned c   = (t >> 16) & 63u;
            unsigned b   = t >> 22;

            unsigned m  = ((sh >> 6) << 3) | (w4 >> 4);  // (sh/64)*8 + (sw/64)
            unsigned s  = (m - c) & 63u;
            unsigned i  = sh & 63u;
            unsigned j4 = w4 & 15u;

            unsigned dst_h  = ((s >> 3) << 6) | i;
            unsigned dst_w4 = ((s & 7u) << 4) | j4;
            unsigned base   = ((b << 6) | c) << 16;      // 65536 float4/image

            dst[k] = base + (dst_h << 7) + dst_w4;
            add[k] = __ldg(&ap[(c << 6) | m]);
        }

#pragma unroll
        for (int k = 0; k < 4; ++k) {
            float a = add[k];
            v[k].x += a; v[k].y += a; v[k].z += a; v[k].w += a;
            __stcs(&out[dst[k]], v[k]);            // 256B-coalesced scatter
        }
    }
}

extern "C" void kernel_launch(void* const* d_in, const int* in_sizes, int n_in,
                              void* d_out, int out_size)
{
    const float4* x   = (const float4*)d_in[0];   // (4,64,512,512) fp32
    const float*  ap  = (const float*)d_in[1];    // (1,1,64,64,1,1) fp32
    float4*       out = (float4*)d_out;

    crosspatch_kernel<<<NBLK, 256>>>(x, ap, out);
}

// round 8
// speedup vs baseline: 1.1272x; 1.1272x over previous
#include <cuda_runtime.h>
#include <cuda_bf16.h>
#include <cstdint>

// CrossPatchModule closed form:
//   B=4, C=64, H=W=512, PH=PW=8, PN=64, kh=kw=64
//   ph=h>>6, i=h&63, pw=w>>6, j=w&63
//   s = ph*8+pw;  m=(c+s)&63
//   out[b,c,h,w] = x[b,c, (m>>3)*64 + i, (m&7)*64 + j] + abs_pos[c*64+m]
//
// Pure permutation gather + scalar add; 512MB irreducible traffic, HBM-bound.
// R7: best-measured config (R1: write-linear, read-gather, MLP=4 front-
// batched, streaming hints, grid 16384x256) with k-invariant index math
// hoisted (w4/pw/j4/b/c constant across the 4 unrolled elements).

__global__ __launch_bounds__(256, 8)
void crosspatch_kernel(const float4* __restrict__ x,
                       const float*  __restrict__ ap,
                       float4*       __restrict__ out)
{
    // 4 float4 per thread at stride 256 float4: each warp access is 32
    // consecutive float4 (512B), fully coalesced on both sides.
    unsigned t0 = blockIdx.x * 1024u + threadIdx.x;

    // k-invariant pieces (t0 + k*256 leaves bits 0..6 unchanged; c,b occupy
    // bits 16+ and k*256 < 2^10 cannot carry into them within a 1024 chunk
    // because t0 is 1024-aligned per block up to threadIdx: bits 10..15 may
    // carry from h; c/b bits are safe since h spans bits 7..15 and
    // h0 + 6 < 512 whenever t0's h0 <= 505 -- guaranteed: h0 = (t0>>7)&511,
    // k*256 adds 2 per k to h, and blocks of 1024 float4 never straddle an
    // image boundary (65536 % 1024 == 0), so h0 <= 506 with h0+6 <= 511... 
    // h0 parity: within a block h0 is even-started? t0 spans 1024 float4 =
    // 8 rows, so h0 in [r, r+7] with r ≡ 0 (mod 8); h0+6 <= r+13 < r+... 
    // safe: the 8-row group never crosses image boundary.)
    unsigned w4 = t0 & 127u;
    unsigned pw = w4 >> 4;
    unsigned j4 = w4 & 15u;
    unsigned c  = (t0 >> 16) & 63u;
    unsigned base = (t0 >> 16) << 16;          // ((b*64+c) image) * 65536

    unsigned src[4];
    float    add[4];

#pragma unroll
    for (int k = 0; k < 4; ++k) {
        unsigned h  = ((t0 + k * 256u) >> 7) & 511u;
        unsigned ph = h >> 6;
        unsigned i  = h & 63u;

        unsigned m  = (c + ph * 8u + pw) & 63u;
        unsigned src_h  = ((m >> 3) << 6) | i;
        unsigned src_w4 = ((m & 7u) << 4) | j4;

        src[k] = base + (src_h << 7) + src_w4;
        add[k] = __ldg(&ap[(c << 6) | m]);
    }

    float4 v[4];
#pragma unroll
    for (int k = 0; k < 4; ++k)
        v[k] = __ldcs(&x[src[k]]);             // streaming gather (no reuse)

#pragma unroll
    for (int k = 0; k < 4; ++k) {
        float a = add[k];
        v[k].x += a; v[k].y += a; v[k].z += a; v[k].w += a;
        __stcs(&out[t0 + k * 256u], v[k]);     // sequential streaming write
    }
}

extern "C" void kernel_launch(void* const* d_in, const int* in_sizes, int n_in,
                              void* d_out, int out_size)
{
    const float4* x   = (const float4*)d_in[0];   // (4,64,512,512) fp32
    const float*  ap  = (const float*)d_in[1];    // (1,1,64,64,1,1) fp32
    float4*       out = (float4*)d_out;

    crosspatch_kernel<<<16384, 256>>>(x, ap, out);
}